// round 13
// baseline (speedup 1.0000x reference)
#include <cuda_runtime.h>
#include <cstdint>

#define B_   256
#define T_   128
#define IN_  128
#define H_   256
#define H3_  768
#define OUT_ 128

// ---- persistent recurrence: 64 clusters x 2 CTAs, 12 rows per cluster (proven skeleton)
#define RWS  12                    // (c,b) state rows per cluster
#define NBLK 128                   // CTAs (64 clusters of 2)
#define PTH  256                   // 8 warps; wgid = tid>>7 -> kk-half of each chunk; j = tid&127
#define NCOL 384                   // gate columns per CTA (3 segments of 128)
#define KC   32                    // k rows of Wh per chunk
#define NCHUNK (H_/KC)             // 8
#define NBUF 3
#define CHUNK_BYTES (KC*NCOL*4)    // 49152
#define GX_BYTES (RWS*NCOL*4)      // 18432
#define HSTR 14                    // hst column stride (12 rows + pad, even)
#define HST_FLOATS (H_*HSTR)       // 3584
#define BS_FLOATS  (NBUF*KC*NCOL)  // 36864
#define GXS_FLOATS (RWS*NCOL)      // 4608
#define XCH_FLOATS (9*2*128*2)     // 4608 floats (9 idx x 2 wg x 128 j, uint64 each)
#define SMEM_FLOATS (2*HST_FLOATS + BS_FLOATS + GXS_FLOATS + XCH_FLOATS)  // 53248
#define SMEM_BYTES  (SMEM_FLOATS*4 + 64)                                  // 213056

#define WH2_HALF (H_*NCOL)             // 98304 floats per half
#define GX2_HALF ((size_t)T_*B_*NCOL)  // 12.58M floats per half

// scratch (device globals: allocation-free)
__device__ float g_Wh2[2 * WH2_HALF];            // [q][k][s*128+l] reordered Wh
__device__ float g_gx2[2 * GX2_HALF];            // [q][t*256+b][384] x@Wx+bx, per-half cols
__device__ float g_hT[3 * B_ * H_];              // final hidden state

// ---------------------------------------------------------------- helpers
static __device__ __forceinline__ uint32_t s2u(const void* p) {
    uint32_t a;
    asm("{ .reg .u64 t; cvta.to.shared.u64 t, %1; cvt.u32.u64 %0, t; }"
        : "=r"(a) : "l"(p));
    return a;
}
static __device__ __forceinline__ void mbar_init(uint32_t m, int cnt) {
    asm volatile("mbarrier.init.shared.b64 [%0], %1;" :: "r"(m), "r"(cnt) : "memory");
}
static __device__ __forceinline__ void mbar_expect(uint32_t m, uint32_t bytes) {
    asm volatile("mbarrier.arrive.expect_tx.shared.b64 _, [%0], %1;"
                 :: "r"(m), "r"(bytes) : "memory");
}
static __device__ __forceinline__ void mbar_wait(uint32_t m, int ph) {
    asm volatile(
        "{\n\t"
        ".reg .pred P;\n\t"
        "WL%=:\n\t"
        "mbarrier.try_wait.parity.acquire.cta.shared::cta.b64 P, [%0], %1;\n\t"
        "@P bra WD%=;\n\t"
        "bra WL%=;\n\t"
        "WD%=:\n\t"
        "}"
        :: "r"(m), "r"(ph) : "memory");
}
static __device__ __forceinline__ void bulk_g2s(uint32_t dst, const void* src,
                                                uint32_t bytes, uint32_t m) {
    asm volatile(
        "cp.async.bulk.shared::cluster.global.mbarrier::complete_tx::bytes [%0], [%1], %2, [%3];"
        :: "r"(dst), "l"(src), "r"(bytes), "r"(m) : "memory");
}
static __device__ __forceinline__ void fence_async() {
    asm volatile("fence.proxy.async.shared::cta;" ::: "memory");
}
static __device__ __forceinline__ uint32_t mapa_u32(uint32_t addr, uint32_t rank) {
    uint32_t r;
    asm("mapa.shared::cluster.u32 %0, %1, %2;" : "=r"(r) : "r"(addr), "r"(rank));
    return r;
}
static __device__ __forceinline__ void st_cluster_b64(uint32_t addr, uint64_t v) {
    asm volatile("st.shared::cluster.b64 [%0], %1;" :: "r"(addr), "l"(v) : "memory");
}
#define CLUSTER_ARRIVE() asm volatile("barrier.cluster.arrive.aligned;" ::: "memory")
#define CLUSTER_WAIT()   asm volatile("barrier.cluster.wait.aligned;"   ::: "memory")

// packed fp32x2 ops
static __device__ __forceinline__ uint64_t pack2(float v) {
    uint64_t r;
    asm("mov.b64 %0, {%1, %1};" : "=l"(r) : "f"(v));
    return r;
}
static __device__ __forceinline__ uint64_t pack2f(float lo, float hi) {
    uint64_t r;
    asm("mov.b64 %0, {%1, %2};" : "=l"(r) : "f"(lo), "f"(hi));
    return r;
}
static __device__ __forceinline__ void fma2(uint64_t& d, uint64_t a, uint64_t b) {
    asm("fma.rn.f32x2 %0, %1, %2, %0;" : "+l"(d) : "l"(a), "l"(b));
}
static __device__ __forceinline__ uint64_t addf2(uint64_t a, uint64_t b) {
    uint64_t o;
    asm("add.rn.f32x2 %0, %1, %2;" : "=l"(o) : "l"(a), "l"(b));
    return o;
}
static __device__ __forceinline__ float f32x2_lo(uint64_t v) {
    return __uint_as_float((uint32_t)v);
}
static __device__ __forceinline__ float f32x2_hi(uint64_t v) {
    return __uint_as_float((uint32_t)(v >> 32));
}
static __device__ __forceinline__ float sigmoidf_(float x) {
    return __fdividef(1.0f, 1.0f + __expf(-x));
}
static __device__ __forceinline__ float tanhf_(float x) {
    float ax = fabsf(x);
    float t  = __expf(-2.0f * ax);
    float r  = __fdividef(1.0f - t, 1.0f + t);
    return x >= 0.0f ? r : -r;
}

// ---------------------------------------------------------------- Wh reorder
// g_Wh2[q][k][s*128+l] = Wh[k][s*256 + q*128 + l]
__global__ void __launch_bounds__(256) k_prep(const float* __restrict__ Wh) {
    const int q = blockIdx.y;
    const int e = blockIdx.x * 256 + threadIdx.x;    // 0..98303
    const int k = e / NCOL;
    const int rem = e - k * NCOL;
    const int s = rem >> 7, l = rem & 127;
    g_Wh2[q * WH2_HALF + e] = Wh[k * H3_ + s * 256 + q * 128 + l];
}

// ---------------------------------------------------------------- gx = x @ Wx + bx  (FFMA2)
// Output per-half: g_gx2[q][m][ s*128 + (n&127) ], m = t*256+b.
__global__ void __launch_bounds__(256) k_gx(const float* __restrict__ x,
                                            const float* __restrict__ Wx,
                                            const float* __restrict__ bx) {
    __shared__ float As[16 * 66];
    __shared__ float Bs[16 * 64];
    const int tid = threadIdx.x;
    const int tx = tid & 15, ty = tid >> 4;
    const int n0 = blockIdx.x * 64;
    const int m0 = blockIdx.y * 64;

    uint64_t acc2[2][4];
#pragma unroll
    for (int p = 0; p < 2; p++)
#pragma unroll
        for (int c = 0; c < 4; c++) acc2[p][c] = 0ULL;

    for (int k0 = 0; k0 < IN_; k0 += 16) {
#pragma unroll
        for (int i = 0; i < 4; i++) {
            int e  = tid + i * 256;
            int mm = e >> 4, kk = e & 15;
            int m  = m0 + mm;
            int tt = m >> 8, bb = m & 255;
            As[kk * 66 + mm] = x[bb * (T_ * IN_) + tt * IN_ + k0 + kk];
        }
#pragma unroll
        for (int i = 0; i < 4; i++) {
            int e  = tid + i * 256;
            int kk = e >> 6, nn = e & 63;
            Bs[kk * 64 + nn] = Wx[(k0 + kk) * H3_ + n0 + nn];
        }
        __syncthreads();
#pragma unroll
        for (int kk = 0; kk < 16; kk++) {
            uint64_t a01 = *(const uint64_t*)&As[kk * 66 + ty * 4];
            uint64_t a23 = *(const uint64_t*)&As[kk * 66 + ty * 4 + 2];
            float4 b4 = *(const float4*)&Bs[kk * 64 + tx * 4];
            uint64_t p0 = pack2(b4.x), p1 = pack2(b4.y);
            uint64_t p2 = pack2(b4.z), p3 = pack2(b4.w);
            fma2(acc2[0][0], a01, p0); fma2(acc2[0][1], a01, p1);
            fma2(acc2[0][2], a01, p2); fma2(acc2[0][3], a01, p3);
            fma2(acc2[1][0], a23, p0); fma2(acc2[1][1], a23, p1);
            fma2(acc2[1][2], a23, p2); fma2(acc2[1][3], a23, p3);
        }
        __syncthreads();
    }
    const int n = n0 + tx * 4;                 // global col; all 4 in same (s,q) block
    const int q = (n >> 7) & 1;
    const int c384 = (n >> 8) * 128 + (n & 127);
    float4 bxv = *(const float4*)&bx[n];
    float* dst = g_gx2 + (size_t)q * GX2_HALF + c384;
#pragma unroll
    for (int p = 0; p < 2; p++) {
        float4 lo4, hi4;
        lo4.x = f32x2_lo(acc2[p][0]) + bxv.x;  hi4.x = f32x2_hi(acc2[p][0]) + bxv.x;
        lo4.y = f32x2_lo(acc2[p][1]) + bxv.y;  hi4.y = f32x2_hi(acc2[p][1]) + bxv.y;
        lo4.z = f32x2_lo(acc2[p][2]) + bxv.z;  hi4.z = f32x2_hi(acc2[p][2]) + bxv.z;
        lo4.w = f32x2_lo(acc2[p][3]) + bxv.w;  hi4.w = f32x2_hi(acc2[p][3]) + bxv.w;
        *(float4*)(dst + (size_t)(m0 + ty * 4 + 2 * p)     * NCOL) = lo4;
        *(float4*)(dst + (size_t)(m0 + ty * 4 + 2 * p + 1) * NCOL) = hi4;
    }
}

// ---------------------------------------------------------------- persistent CRU recurrence
// 64 clusters of 2 CTAs — EXACT skeleton of the 1375us kernel (same ring, same
// barriers, same prefetch, same cluster arrive/wait). Only the inner loop changes:
// IN-CHUNK K-SPLIT — wg0 processes kk 0..15 of every chunk, wg1 kk 16..31, each
// accumulating partial gh for ALL 12 rows. B duplication across warp-groups is
// eliminated: crossbar 9216 = FMA 9216 cyc/step (was 12288 crossbar-bound).
// One SMEM exchange-reduce per step, then the identical epilogue
// (wg0 gates rows 0-5, wg1 rows 6-11).
__global__ void __launch_bounds__(PTH) __cluster_dims__(2, 1, 1)
k_cru(const float* __restrict__ h0, const float* __restrict__ bh) {
    extern __shared__ float sm[];
    float* hst0 = sm;                                   // [256][HSTR] h buffer 0
    float* hst1 = sm + HST_FLOATS;                      // [256][HSTR] h buffer 1
    float* Bs   = sm + 2 * HST_FLOATS;                  // [NBUF][KC][384] Wh chunks
    float* gxs  = sm + 2 * HST_FLOATS + BS_FLOATS;      // [12][384] gx tile
    uint64_t* xch = (uint64_t*)(gxs + GXS_FLOATS);      // [9][2][128] partial exchange
    uint64_t* mb = (uint64_t*)(sm + SMEM_FLOATS);       // 3 Wh + 1 gx barriers

    const int tid  = threadIdx.x;
    const int wgid = tid >> 7;          // kk-half of each chunk (0: kk<16, 1: kk>=16)
    const int j    = tid & 127;
    const int q    = blockIdx.x & 1;    // cluster rank
    const int q4   = 4 * q;             // first own chunk
    const int r0   = (blockIdx.x >> 1) * RWS;
    const int b_base = r0 & (B_ - 1);
    const int jh   = q * 128 + j;       // owned h column
    const int kk0  = 16 * wgid;         // this wg's kk range within a chunk

    uint32_t mbw[NBUF], mbg;
#pragma unroll
    for (int i = 0; i < NBUF; i++) mbw[i] = s2u(mb + i);
    mbg = s2u(mb + NBUF);
    const uint32_t bsu  = s2u(Bs);
    const uint32_t gxsu = s2u(gxs);
    const uint32_t h0u  = s2u(hst0);
    const uint32_t h1u  = s2u(hst1);
    const uint32_t peer_h0 = mapa_u32(h0u, q ^ 1);
    const uint32_t peer_h1 = mapa_u32(h1u, q ^ 1);
    const float* whq = g_Wh2 + q * WH2_HALF;

    // initial h: h0[(r0+r)*H + k] -> hst0[k*HSTR + r]
    for (int idx = tid; idx < RWS * H_; idx += PTH) {
        const int r = idx >> 8, k = idx & 255;
        hst0[k * HSTR + r] = h0[(r0 + r) * H_ + k];
    }

    // bh for owned column (added once: wg0's accumulator init)
    uint64_t bh2[3];
#pragma unroll
    for (int s = 0; s < 3; s++) bh2[s] = pack2(bh[s * H_ + jh]);

    if (tid == 0) {
#pragma unroll
        for (int i = 0; i < NBUF; i++) mbar_init(mbw[i], 1);
        mbar_init(mbg, 1);
        fence_async();
    }
    __syncthreads();

    // prologue: 3 Wh chunks (own-first order) + gx(t=0)
    if (tid == 0) {
#pragma unroll
        for (int i = 0; i < NBUF; i++) {
            const int ch = (q4 + i) & (NCHUNK - 1);
            mbar_expect(mbw[i], CHUNK_BYTES);
            bulk_g2s(bsu + i * CHUNK_BYTES, whq + ch * (KC * NCOL), CHUNK_BYTES, mbw[i]);
        }
        const int n1 = (b_base + RWS > B_) ? (B_ - b_base) : RWS;
        mbar_expect(mbg, GX_BYTES);
        bulk_g2s(gxsu, g_gx2 + (size_t)q * GX2_HALF + (size_t)b_base * NCOL,
                 n1 * NCOL * 4, mbg);
        if (n1 < RWS)
            bulk_g2s(gxsu + n1 * NCOL * 4, g_gx2 + (size_t)q * GX2_HALF,
                     (RWS - n1) * NCOL * 4, mbg);
    }

    int phw[NBUF] = {0, 0, 0};
    int phg = 0;
    int cc = 0;
    const int CCMAX = NCHUNK * T_;
    const int give = wgid ? 0 : 3;      // row pairs handed to the other wg
    const int keep = wgid ? 3 : 0;      // row pairs this wg finalizes

    CLUSTER_ARRIVE();   // pairs with the wait inside step 0's GEMM

    for (int t = 0; t < T_; t++) {
        const float* hcur = (t & 1) ? hst1 : hst0;
        float* hnxt = (t & 1) ? hst0 : hst1;
        const uint32_t hn_peer = (t & 1) ? peer_h0 : peer_h1;

        // partial gh for ALL 12 rows over this wg's kk-half; bh counted once (wg0)
        uint64_t acc[6][3];
#pragma unroll
        for (int p = 0; p < 6; p++)
#pragma unroll
            for (int s = 0; s < 3; s++) acc[p][s] = wgid ? 0ULL : bh2[s];

        for (int i = 0; i < NCHUNK; i++) {
            if (i == 4) CLUSTER_WAIT();   // peer h columns needed from here on

            const int buf = cc % NBUF;
            mbar_wait(mbw[buf], phw[buf]);
            phw[buf] ^= 1;

            const int ch = (q4 + i) & (NCHUNK - 1);
            const float* bp = Bs + buf * (KC * NCOL) + kk0 * NCOL + j;
            const float* hp = hcur + ch * (KC * HSTR) + kk0 * HSTR;
#pragma unroll
            for (int kk = 0; kk < 16; kk++) {
                uint64_t a0 = *(const uint64_t*)(hp + kk * HSTR + 0);
                uint64_t a1 = *(const uint64_t*)(hp + kk * HSTR + 2);
                uint64_t a2 = *(const uint64_t*)(hp + kk * HSTR + 4);
                uint64_t a3 = *(const uint64_t*)(hp + kk * HSTR + 6);
                uint64_t a4 = *(const uint64_t*)(hp + kk * HSTR + 8);
                uint64_t a5 = *(const uint64_t*)(hp + kk * HSTR + 10);
                uint64_t p0 = pack2(bp[kk * NCOL]);
                uint64_t p1 = pack2(bp[kk * NCOL + 128]);
                uint64_t p2 = pack2(bp[kk * NCOL + 256]);
                fma2(acc[0][0], a0, p0); fma2(acc[0][1], a0, p1); fma2(acc[0][2], a0, p2);
                fma2(acc[1][0], a1, p0); fma2(acc[1][1], a1, p1); fma2(acc[1][2], a1, p2);
                fma2(acc[2][0], a2, p0); fma2(acc[2][1], a2, p1); fma2(acc[2][2], a2, p2);
                fma2(acc[3][0], a3, p0); fma2(acc[3][1], a3, p1); fma2(acc[3][2], a3, p2);
                fma2(acc[4][0], a4, p0); fma2(acc[4][1], a4, p1); fma2(acc[4][2], a4, p2);
                fma2(acc[5][0], a5, p0); fma2(acc[5][1], a5, p1); fma2(acc[5][2], a5, p2);
            }
            __syncthreads();   // both wgs done with this buffer
            if (tid == 0 && cc + NBUF < CCMAX) {
                const int nch = (q4 + ((cc + NBUF) & (NCHUNK - 1))) & (NCHUNK - 1);
                const uint32_t m = mbw[buf];
                mbar_expect(m, CHUNK_BYTES);
                bulk_g2s(bsu + buf * CHUNK_BYTES, whq + nch * (KC * NCOL), CHUNK_BYTES, m);
            }
            cc++;
        }

        // ---- exchange-reduce partials between warp-groups
#pragma unroll
        for (int pl = 0; pl < 3; pl++)
#pragma unroll
            for (int s = 0; s < 3; s++)
                xch[((pl * 3 + s) * 2 + wgid) * 128 + j] = acc[give + pl][s];
        __syncthreads();
#pragma unroll
        for (int pl = 0; pl < 3; pl++)
#pragma unroll
            for (int s = 0; s < 3; s++)
                acc[keep + pl][s] = addf2(acc[keep + pl][s],
                                          xch[((pl * 3 + s) * 2 + (wgid ^ 1)) * 128 + j]);

        // ---- gate epilogue: rows 6*wgid .. 6*wgid+5, col jh (identical to 1375us kernel)
        mbar_wait(mbg, phg); phg ^= 1;
#pragma unroll
        for (int pl = 0; pl < 3; pl++) {
            const int P = keep + pl;
            float nv[2];
#pragma unroll
            for (int hi = 0; hi < 2; hi++) {
                const int R = 6 * wgid + 2 * pl + hi;   // cluster row
                const float hr = hi ? f32x2_hi(acc[P][0]) : f32x2_lo(acc[P][0]);
                const float hz = hi ? f32x2_hi(acc[P][1]) : f32x2_lo(acc[P][1]);
                const float hn = hi ? f32x2_hi(acc[P][2]) : f32x2_lo(acc[P][2]);
                const float xr = gxs[R * NCOL + j];
                const float xz = gxs[R * NCOL + 128 + j];
                const float xn = gxs[R * NCOL + 256 + j];
                const float rg = sigmoidf_(xr + hr);
                const float zg = sigmoidf_(xz + hz);
                const float ng = tanhf_(xn + rg * hn);
                const float ho = hcur[jh * HSTR + R];
                nv[hi] = ng + zg * (ho - ng);
            }
            const uint64_t pr = pack2f(nv[0], nv[1]);
            const int off = jh * HSTR + 6 * wgid + 2 * pl;
            *(uint64_t*)(hnxt + off) = pr;                       // local
            st_cluster_b64(hn_peer + (uint32_t)off * 4u, pr);    // peer
        }

        __syncthreads();   // local h writes visible; gxs + xch fully consumed

        if (tid == 0 && t + 1 < T_) {
            const int n1 = (b_base + RWS > B_) ? (B_ - b_base) : RWS;
            mbar_expect(mbg, GX_BYTES);
            bulk_g2s(gxsu, g_gx2 + (size_t)q * GX2_HALF +
                     ((size_t)(t + 1) * B_ + b_base) * NCOL, n1 * NCOL * 4, mbg);
            if (n1 < RWS)
                bulk_g2s(gxsu + n1 * NCOL * 4,
                         g_gx2 + (size_t)q * GX2_HALF + (size_t)(t + 1) * B_ * NCOL,
                         (RWS - n1) * NCOL * 4, mbg);
        }

        CLUSTER_ARRIVE();   // releases peer h stores; consumed at next step's i==4
    }

    CLUSTER_WAIT();    // drain final phase; peer remote stores complete before exit

    // final h (T even -> hst0); each CTA stores its own column half
    for (int idx = tid; idx < RWS * 128; idx += PTH) {
        const int r = idx >> 7, l = idx & 127;
        g_hT[(r0 + r) * H_ + q * 128 + l] = hst0[(q * 128 + l) * HSTR + r];
    }
}

// ---------------------------------------------------------------- out = elu((sum_c hT) @ Wf + bf)
__global__ void __launch_bounds__(128) k_out(const float* __restrict__ Wf,
                                             const float* __restrict__ bf,
                                             float* __restrict__ out) {
    __shared__ float s[H_];
    const int b = blockIdx.x;
    const int tid = threadIdx.x;
    for (int k = tid; k < H_; k += 128)
        s[k] = g_hT[b * H_ + k] + g_hT[B_ * H_ + b * H_ + k] + g_hT[2 * B_ * H_ + b * H_ + k];
    __syncthreads();
    float acc = bf[tid];
#pragma unroll 8
    for (int k = 0; k < H_; k++)
        acc = fmaf(s[k], Wf[k * OUT_ + tid], acc);
    out[b * OUT_ + tid] = acc > 0.0f ? acc : expm1f(acc);
}

// ---------------------------------------------------------------- feature = mean_b hT -> (3, H)
__global__ void __launch_bounds__(256) k_feat(float* __restrict__ feat) {
    __shared__ float p[8][32];
    const int tx = threadIdx.x & 31, ty = threadIdx.x >> 5;
    const int jg = blockIdx.x * 32 + tx;            // 0..767
    const int c = jg >> 8, j = jg & 255;
    float s = 0.0f;
#pragma unroll 8
    for (int i = 0; i < 32; i++) {
        const int b = ty * 32 + i;
        s += g_hT[c * (B_ * H_) + b * H_ + j];
    }
    p[ty][tx] = s;
    __syncthreads();
    if (ty == 0) {
        float acc = 0.0f;
#pragma unroll
        for (int qq = 0; qq < 8; qq++) acc += p[qq][tx];
        feat[jg] = acc * (1.0f / 256.0f);
    }
}

// ---------------------------------------------------------------- launch
extern "C" void kernel_launch(void* const* d_in, const int* in_sizes, int n_in,
                              void* d_out, int out_size) {
    const float* x  = (const float*)d_in[0];
    const float* h0 = (const float*)d_in[1];
    const float* Wx = (const float*)d_in[2];
    const float* bx = (const float*)d_in[3];
    const float* Wh = (const float*)d_in[4];
    const float* bh = (const float*)d_in[5];
    const float* Wf = (const float*)d_in[6];
    const float* bf = (const float*)d_in[7];
    float* out = (float*)d_out;

    cudaFuncSetAttribute(k_cru, cudaFuncAttributeMaxDynamicSharedMemorySize, SMEM_BYTES);

    dim3 gp(WH2_HALF / 256, 2);          // (384, 2)
    k_prep<<<gp, 256>>>(Wh);
    dim3 g1(H3_ / 64, (T_ * B_) / 64);   // (12, 512)
    k_gx<<<g1, 256>>>(x, Wx, bx);
    k_cru<<<NBLK, PTH, SMEM_BYTES>>>(h0, bh);
    k_out<<<B_, 128>>>(Wf, bf, out);
    k_feat<<<24, 256>>>(out + (out_size - 3 * H_));
}

// round 14
// speedup vs baseline: 1.2654x; 1.2654x over previous
#include <cuda_runtime.h>
#include <cstdint>

#define B_   256
#define T_   128
#define IN_  128
#define H_   256
#define H3_  768
#define OUT_ 128

// ---- persistent recurrence: 64 clusters x 2 CTAs, 12 rows per cluster (champion skeleton)
#define RWS  12                    // (c,b) state rows per cluster
#define NBLK 128                   // CTAs (64 clusters of 2)
#define PTH  256                   // 8 warps; wg = tid>>7 -> rows 6wg..6wg+5; j = tid&127
#define NCOL 384                   // gate columns per CTA (3 segments of 128)
#define KC   32                    // k rows of Wh per chunk
#define NCHUNK (H_/KC)             // 8
#define NBUF 3
#define CHUNK_BYTES (KC*NCOL*4)    // 49152
#define GX_BYTES (RWS*NCOL*4)      // 18432
#define HSTR 14                    // hst column stride (12 rows + 2 pad)
#define HST_FLOATS (H_*HSTR)       // 3584
#define BS_FLOATS  (NBUF*KC*NCOL)  // 36864
#define GXS_FLOATS (RWS*NCOL)      // 4608
#define SMEM_FLOATS (2*HST_FLOATS + BS_FLOATS + GXS_FLOATS)   // 48640
#define SMEM_BYTES  (SMEM_FLOATS*4 + 64)                      // 194624 (+7 mbarriers)

#define WH2_HALF (H_*NCOL)             // 98304 floats per half
#define GX2_HALF ((size_t)T_*B_*NCOL)  // 12.58M floats per half

// scratch (device globals: allocation-free)
__device__ float g_Wh2[2 * WH2_HALF];            // [q][k][s*128+l] reordered Wh
__device__ float g_gx2[2 * GX2_HALF];            // [q][t*256+b][384] x@Wx+bx, per-half cols
__device__ float g_hT[3 * B_ * H_];              // final hidden state

// ---------------------------------------------------------------- helpers
static __device__ __forceinline__ uint32_t s2u(const void* p) {
    uint32_t a;
    asm("{ .reg .u64 t; cvta.to.shared.u64 t, %1; cvt.u32.u64 %0, t; }"
        : "=r"(a) : "l"(p));
    return a;
}
static __device__ __forceinline__ void mbar_init(uint32_t m, int cnt) {
    asm volatile("mbarrier.init.shared.b64 [%0], %1;" :: "r"(m), "r"(cnt) : "memory");
}
static __device__ __forceinline__ void mbar_expect(uint32_t m, uint32_t bytes) {
    asm volatile("mbarrier.arrive.expect_tx.shared.b64 _, [%0], %1;"
                 :: "r"(m), "r"(bytes) : "memory");
}
static __device__ __forceinline__ void mbar_arrive(uint32_t m) {
    asm volatile("mbarrier.arrive.shared.b64 _, [%0];" :: "r"(m) : "memory");
}
static __device__ __forceinline__ void mbar_wait(uint32_t m, int ph) {
    asm volatile(
        "{\n\t"
        ".reg .pred P;\n\t"
        "WL%=:\n\t"
        "mbarrier.try_wait.parity.acquire.cta.shared::cta.b64 P, [%0], %1;\n\t"
        "@P bra WD%=;\n\t"
        "bra WL%=;\n\t"
        "WD%=:\n\t"
        "}"
        :: "r"(m), "r"(ph) : "memory");
}
static __device__ __forceinline__ void bulk_g2s(uint32_t dst, const void* src,
                                                uint32_t bytes, uint32_t m) {
    asm volatile(
        "cp.async.bulk.shared::cluster.global.mbarrier::complete_tx::bytes [%0], [%1], %2, [%3];"
        :: "r"(dst), "l"(src), "r"(bytes), "r"(m) : "memory");
}
static __device__ __forceinline__ void fence_async() {
    asm volatile("fence.proxy.async.shared::cta;" ::: "memory");
}
static __device__ __forceinline__ uint32_t mapa_u32(uint32_t addr, uint32_t rank) {
    uint32_t r;
    asm("mapa.shared::cluster.u32 %0, %1, %2;" : "=r"(r) : "r"(addr), "r"(rank));
    return r;
}
static __device__ __forceinline__ void st_cluster_b64(uint32_t addr, uint64_t v) {
    asm volatile("st.shared::cluster.b64 [%0], %1;" :: "r"(addr), "l"(v) : "memory");
}
#define CLUSTER_ARRIVE() asm volatile("barrier.cluster.arrive.aligned;" ::: "memory")
#define CLUSTER_WAIT()   asm volatile("barrier.cluster.wait.aligned;"   ::: "memory")

// packed fp32x2 ops
static __device__ __forceinline__ uint64_t pack2(float v) {
    uint64_t r;
    asm("mov.b64 %0, {%1, %1};" : "=l"(r) : "f"(v));
    return r;
}
static __device__ __forceinline__ uint64_t pack2f(float lo, float hi) {
    uint64_t r;
    asm("mov.b64 %0, {%1, %2};" : "=l"(r) : "f"(lo), "f"(hi));
    return r;
}
static __device__ __forceinline__ void fma2(uint64_t& d, uint64_t a, uint64_t b) {
    asm("fma.rn.f32x2 %0, %1, %2, %0;" : "+l"(d) : "l"(a), "l"(b));
}
static __device__ __forceinline__ float f32x2_lo(uint64_t v) {
    return __uint_as_float((uint32_t)v);
}
static __device__ __forceinline__ float f32x2_hi(uint64_t v) {
    return __uint_as_float((uint32_t)(v >> 32));
}
static __device__ __forceinline__ float sigmoidf_(float x) {
    return __fdividef(1.0f, 1.0f + __expf(-x));
}
static __device__ __forceinline__ float tanhf_(float x) {
    float ax = fabsf(x);
    float t  = __expf(-2.0f * ax);
    float r  = __fdividef(1.0f - t, 1.0f + t);
    return x >= 0.0f ? r : -r;
}

// ---------------------------------------------------------------- Wh reorder
// g_Wh2[q][k][s*128+l] = Wh[k][s*256 + q*128 + l]
__global__ void __launch_bounds__(256) k_prep(const float* __restrict__ Wh) {
    const int q = blockIdx.y;
    const int e = blockIdx.x * 256 + threadIdx.x;    // 0..98303
    const int k = e / NCOL;
    const int rem = e - k * NCOL;
    const int s = rem >> 7, l = rem & 127;
    g_Wh2[q * WH2_HALF + e] = Wh[k * H3_ + s * 256 + q * 128 + l];
}

// ---------------------------------------------------------------- gx = x @ Wx + bx  (FFMA2)
// Output written per-half: g_gx2[q][m][ s*128 + (n&127) ], m = t*256+b.
__global__ void __launch_bounds__(256) k_gx(const float* __restrict__ x,
                                            const float* __restrict__ Wx,
                                            const float* __restrict__ bx) {
    __shared__ float As[16 * 66];
    __shared__ float Bs[16 * 64];
    const int tid = threadIdx.x;
    const int tx = tid & 15, ty = tid >> 4;
    const int n0 = blockIdx.x * 64;
    const int m0 = blockIdx.y * 64;

    uint64_t acc2[2][4];
#pragma unroll
    for (int p = 0; p < 2; p++)
#pragma unroll
        for (int c = 0; c < 4; c++) acc2[p][c] = 0ULL;

    for (int k0 = 0; k0 < IN_; k0 += 16) {
#pragma unroll
        for (int i = 0; i < 4; i++) {
            int e  = tid + i * 256;
            int mm = e >> 4, kk = e & 15;
            int m  = m0 + mm;
            int tt = m >> 8, bb = m & 255;
            As[kk * 66 + mm] = x[bb * (T_ * IN_) + tt * IN_ + k0 + kk];
        }
#pragma unroll
        for (int i = 0; i < 4; i++) {
            int e  = tid + i * 256;
            int kk = e >> 6, nn = e & 63;
            Bs[kk * 64 + nn] = Wx[(k0 + kk) * H3_ + n0 + nn];
        }
        __syncthreads();
#pragma unroll
        for (int kk = 0; kk < 16; kk++) {
            uint64_t a01 = *(const uint64_t*)&As[kk * 66 + ty * 4];
            uint64_t a23 = *(const uint64_t*)&As[kk * 66 + ty * 4 + 2];
            float4 b4 = *(const float4*)&Bs[kk * 64 + tx * 4];
            uint64_t p0 = pack2(b4.x), p1 = pack2(b4.y);
            uint64_t p2 = pack2(b4.z), p3 = pack2(b4.w);
            fma2(acc2[0][0], a01, p0); fma2(acc2[0][1], a01, p1);
            fma2(acc2[0][2], a01, p2); fma2(acc2[0][3], a01, p3);
            fma2(acc2[1][0], a23, p0); fma2(acc2[1][1], a23, p1);
            fma2(acc2[1][2], a23, p2); fma2(acc2[1][3], a23, p3);
        }
        __syncthreads();
    }
    const int n = n0 + tx * 4;                 // global col; all 4 in same (s,q) block
    const int q = (n >> 7) & 1;
    const int c384 = (n >> 8) * 128 + (n & 127);
    float4 bxv = *(const float4*)&bx[n];
    float* dst = g_gx2 + (size_t)q * GX2_HALF + c384;
#pragma unroll
    for (int p = 0; p < 2; p++) {
        float4 lo4, hi4;
        lo4.x = f32x2_lo(acc2[p][0]) + bxv.x;  hi4.x = f32x2_hi(acc2[p][0]) + bxv.x;
        lo4.y = f32x2_lo(acc2[p][1]) + bxv.y;  hi4.y = f32x2_hi(acc2[p][1]) + bxv.y;
        lo4.z = f32x2_lo(acc2[p][2]) + bxv.z;  hi4.z = f32x2_hi(acc2[p][2]) + bxv.z;
        lo4.w = f32x2_lo(acc2[p][3]) + bxv.w;  hi4.w = f32x2_hi(acc2[p][3]) + bxv.w;
        *(float4*)(dst + (size_t)(m0 + ty * 4 + 2 * p)     * NCOL) = lo4;
        *(float4*)(dst + (size_t)(m0 + ty * 4 + 2 * p + 1) * NCOL) = hi4;
    }
}

// ---------------------------------------------------------------- persistent CRU recurrence
// EXACT champion (1375us) structure and inner loop; the ONLY change: the 8 per-chunk
// block-wide __syncthreads are replaced by the canonical full/empty mbarrier pair.
// Each warp's lane 0 arrives on empty[buf] (count=8) after consuming a chunk; tid0
// waits empty[buf] before re-issuing the TMA. Warps may slip up to 2 chunks,
// hiding full-waits and prefetch work; one __syncthreads per step remains.
__global__ void __launch_bounds__(PTH) __cluster_dims__(2, 1, 1)
k_cru(const float* __restrict__ h0, const float* __restrict__ bh) {
    extern __shared__ float sm[];
    float* hst0 = sm;                                   // [256][HSTR] h buffer 0
    float* hst1 = sm + HST_FLOATS;                      // [256][HSTR] h buffer 1
    float* Bs   = sm + 2 * HST_FLOATS;                  // [NBUF][KC][384] Wh chunks
    float* gxs  = sm + 2 * HST_FLOATS + BS_FLOATS;      // [12][384] gx tile
    uint64_t* mb = (uint64_t*)(sm + SMEM_FLOATS);       // 3 full + 1 gx + 3 empty

    const int tid = threadIdx.x;
    const int wg  = tid >> 7;           // 0/1 -> rows 6wg..6wg+5
    const int j   = tid & 127;
    const int q   = blockIdx.x & 1;     // cluster rank
    const int q4  = 4 * q;              // first own chunk
    const int r0  = (blockIdx.x >> 1) * RWS;
    const int b_base = r0 & (B_ - 1);
    const int jh  = q * 128 + j;        // owned h column

    uint32_t mbw[NBUF], mbg, mbe[NBUF];
#pragma unroll
    for (int i = 0; i < NBUF; i++) mbw[i] = s2u(mb + i);
    mbg = s2u(mb + NBUF);
#pragma unroll
    for (int i = 0; i < NBUF; i++) mbe[i] = s2u(mb + NBUF + 1 + i);
    const uint32_t bsu  = s2u(Bs);
    const uint32_t gxsu = s2u(gxs);
    const uint32_t h0u  = s2u(hst0);
    const uint32_t h1u  = s2u(hst1);
    const uint32_t peer_h0 = mapa_u32(h0u, q ^ 1);
    const uint32_t peer_h1 = mapa_u32(h1u, q ^ 1);
    const float* whq = g_Wh2 + q * WH2_HALF;

    // initial h: h0[(r0+r)*H + k] -> hst0[k*HSTR + r]
    for (int idx = tid; idx < RWS * H_; idx += PTH) {
        const int r = idx >> 8, k = idx & 255;
        hst0[k * HSTR + r] = h0[(r0 + r) * H_ + k];
    }

    uint64_t bh2[3];
#pragma unroll
    for (int g = 0; g < 3; g++) bh2[g] = pack2(bh[g * H_ + jh]);

    if (tid == 0) {
#pragma unroll
        for (int i = 0; i < NBUF; i++) mbar_init(mbw[i], 1);
        mbar_init(mbg, 1);
#pragma unroll
        for (int i = 0; i < NBUF; i++) mbar_init(mbe[i], 8);   // one arrive per warp
        fence_async();
    }
    __syncthreads();

    // prologue: 3 Wh chunks (own-first order) + gx(t=0); buffers start empty
    if (tid == 0) {
#pragma unroll
        for (int i = 0; i < NBUF; i++) {
            const int ch = (q4 + i) & (NCHUNK - 1);
            mbar_expect(mbw[i], CHUNK_BYTES);
            bulk_g2s(bsu + i * CHUNK_BYTES, whq + ch * (KC * NCOL), CHUNK_BYTES, mbw[i]);
        }
        const int n1 = (b_base + RWS > B_) ? (B_ - b_base) : RWS;
        mbar_expect(mbg, GX_BYTES);
        bulk_g2s(gxsu, g_gx2 + (size_t)q * GX2_HALF + (size_t)b_base * NCOL,
                 n1 * NCOL * 4, mbg);
        if (n1 < RWS)
            bulk_g2s(gxsu + n1 * NCOL * 4, g_gx2 + (size_t)q * GX2_HALF,
                     (RWS - n1) * NCOL * 4, mbg);
    }

    int phw[NBUF] = {0, 0, 0};          // full-barrier phases (per warp, identical)
    int phe[NBUF] = {0, 0, 0};          // empty-barrier phases (tid0 only uses)
    int phg = 0;
    int cc = 0;
    const int CCMAX = NCHUNK * T_;

    CLUSTER_ARRIVE();   // pairs with the wait inside step 0's GEMM

    for (int t = 0; t < T_; t++) {
        const float* hcur = (t & 1) ? hst1 : hst0;
        const uint32_t hn_loc  = (t & 1) ? h0u : h1u;
        const uint32_t hn_peer = (t & 1) ? peer_h0 : peer_h1;

        uint64_t acc[3][3];
#pragma unroll
        for (int p = 0; p < 3; p++)
#pragma unroll
            for (int g = 0; g < 3; g++) acc[p][g] = bh2[g];

        for (int i = 0; i < NCHUNK; i++) {
            if (i == 4) CLUSTER_WAIT();   // peer h columns needed from here on

            const int buf = cc % NBUF;
            mbar_wait(mbw[buf], phw[buf]);
            phw[buf] ^= 1;

            const int ch = (q4 + i) & (NCHUNK - 1);
            const float* bp = Bs + buf * (KC * NCOL) + j;
            const float* hp = hcur + ch * (KC * HSTR) + 6 * wg;
#pragma unroll
            for (int kk = 0; kk < KC; kk++) {
                uint64_t a01 = *(const uint64_t*)(hp + kk * HSTR + 0);
                uint64_t a23 = *(const uint64_t*)(hp + kk * HSTR + 2);
                uint64_t a45 = *(const uint64_t*)(hp + kk * HSTR + 4);
                uint64_t p0 = pack2(bp[kk * NCOL]);
                uint64_t p1 = pack2(bp[kk * NCOL + 128]);
                uint64_t p2 = pack2(bp[kk * NCOL + 256]);
                fma2(acc[0][0], a01, p0); fma2(acc[0][1], a01, p1); fma2(acc[0][2], a01, p2);
                fma2(acc[1][0], a23, p0); fma2(acc[1][1], a23, p1); fma2(acc[1][2], a23, p2);
                fma2(acc[2][0], a45, p0); fma2(acc[2][1], a45, p1); fma2(acc[2][2], a45, p2);
            }
            // consumer arrive: this warp is done with buf
            if ((tid & 31) == 0) mbar_arrive(mbe[buf]);
            // producer: wait all 8 warps done, then re-issue into buf
            if (tid == 0 && cc + NBUF < CCMAX) {
                mbar_wait(mbe[buf], phe[buf]);
                phe[buf] ^= 1;
                const int nch = (q4 + ((cc + NBUF) & (NCHUNK - 1))) & (NCHUNK - 1);
                mbar_expect(mbw[buf], CHUNK_BYTES);
                bulk_g2s(bsu + buf * CHUNK_BYTES, whq + nch * (KC * NCOL),
                         CHUNK_BYTES, mbw[buf]);
            }
            cc++;
        }

        // gate epilogue — register-resident, write h(next) locally and to peer
        mbar_wait(mbg, phg); phg ^= 1;
#pragma unroll
        for (int p = 0; p < 3; p++) {
            float nv[2];
#pragma unroll
            for (int hi = 0; hi < 2; hi++) {
                const int r = 6 * wg + 2 * p + hi;
                const float hr = hi ? f32x2_hi(acc[p][0]) : f32x2_lo(acc[p][0]);
                const float hz = hi ? f32x2_hi(acc[p][1]) : f32x2_lo(acc[p][1]);
                const float hn = hi ? f32x2_hi(acc[p][2]) : f32x2_lo(acc[p][2]);
                const float xr = gxs[r * NCOL + j];
                const float xz = gxs[r * NCOL + 128 + j];
                const float xn = gxs[r * NCOL + 256 + j];
                const float rg = sigmoidf_(xr + hr);
                const float zg = sigmoidf_(xz + hz);
                const float ng = tanhf_(xn + rg * hn);
                const float ho = hcur[jh * HSTR + r];
                nv[hi] = ng + zg * (ho - ng);
            }
            const uint64_t pr = pack2f(nv[0], nv[1]);
            const uint32_t off = (uint32_t)(jh * HSTR + 6 * wg + 2 * p) * 4u;
            *(uint64_t*)((char*)sm + (hn_loc - s2u(sm)) + off) = pr;  // local store
            st_cluster_b64(hn_peer + off, pr);                        // peer store
        }

        __syncthreads();   // h(next) local writes visible; gxs fully consumed

        if (tid == 0 && t + 1 < T_) {
            const int n1 = (b_base + RWS > B_) ? (B_ - b_base) : RWS;
            mbar_expect(mbg, GX_BYTES);
            bulk_g2s(gxsu, g_gx2 + (size_t)q * GX2_HALF +
                     ((size_t)(t + 1) * B_ + b_base) * NCOL, n1 * NCOL * 4, mbg);
            if (n1 < RWS)
                bulk_g2s(gxsu + n1 * NCOL * 4,
                         g_gx2 + (size_t)q * GX2_HALF + (size_t)(t + 1) * B_ * NCOL,
                         (RWS - n1) * NCOL * 4, mbg);
        }

        CLUSTER_ARRIVE();   // releases peer h stores; consumed at next step's i==4
    }

    CLUSTER_WAIT();    // drain final phase; peer remote stores complete before exit

    // final h (T even -> hst0); each CTA stores its own column half
    for (int idx = tid; idx < RWS * 128; idx += PTH) {
        const int r = idx >> 7, l = idx & 127;
        g_hT[(r0 + r) * H_ + q * 128 + l] = hst0[(q * 128 + l) * HSTR + r];
    }
}

// ---------------------------------------------------------------- out = elu((sum_c hT) @ Wf + bf)
__global__ void __launch_bounds__(128) k_out(const float* __restrict__ Wf,
                                             const float* __restrict__ bf,
                                             float* __restrict__ out) {
    __shared__ float s[H_];
    const int b = blockIdx.x;
    const int tid = threadIdx.x;
    for (int k = tid; k < H_; k += 128)
        s[k] = g_hT[b * H_ + k] + g_hT[B_ * H_ + b * H_ + k] + g_hT[2 * B_ * H_ + b * H_ + k];
    __syncthreads();
    float acc = bf[tid];
#pragma unroll 8
    for (int k = 0; k < H_; k++)
        acc = fmaf(s[k], Wf[k * OUT_ + tid], acc);
    out[b * OUT_ + tid] = acc > 0.0f ? acc : expm1f(acc);
}

// ---------------------------------------------------------------- feature = mean_b hT -> (3, H)
__global__ void __launch_bounds__(256) k_feat(float* __restrict__ feat) {
    __shared__ float p[8][32];
    const int tx = threadIdx.x & 31, ty = threadIdx.x >> 5;
    const int jg = blockIdx.x * 32 + tx;            // 0..767
    const int c = jg >> 8, j = jg & 255;
    float s = 0.0f;
#pragma unroll 8
    for (int i = 0; i < 32; i++) {
        const int b = ty * 32 + i;
        s += g_hT[c * (B_ * H_) + b * H_ + j];
    }
    p[ty][tx] = s;
    __syncthreads();
    if (ty == 0) {
        float acc = 0.0f;
#pragma unroll
        for (int qq = 0; qq < 8; qq++) acc += p[qq][tx];
        feat[jg] = acc * (1.0f / 256.0f);
    }
}

// ---------------------------------------------------------------- launch
extern "C" void kernel_launch(void* const* d_in, const int* in_sizes, int n_in,
                              void* d_out, int out_size) {
    const float* x  = (const float*)d_in[0];
    const float* h0 = (const float*)d_in[1];
    const float* Wx = (const float*)d_in[2];
    const float* bx = (const float*)d_in[3];
    const float* Wh = (const float*)d_in[4];
    const float* bh = (const float*)d_in[5];
    const float* Wf = (const float*)d_in[6];
    const float* bf = (const float*)d_in[7];
    float* out = (float*)d_out;

    cudaFuncSetAttribute(k_cru, cudaFuncAttributeMaxDynamicSharedMemorySize, SMEM_BYTES);

    dim3 gp(WH2_HALF / 256, 2);          // (384, 2)
    k_prep<<<gp, 256>>>(Wh);
    dim3 g1(H3_ / 64, (T_ * B_) / 64);   // (12, 512)
    k_gx<<<g1, 256>>>(x, Wx, bx);
    k_cru<<<NBLK, PTH, SMEM_BYTES>>>(h0, bh);
    k_out<<<B_, 128>>>(Wf, bf, out);
    k_feat<<<24, 256>>>(out + (out_size - 3 * H_));
}